// round 12
// baseline (speedup 1.0000x reference)
#include <cuda_runtime.h>
#include <math.h>

#define W 1024
#define H 1024
#define B 4
#define NPTS 262144
#define HW (W * H)

// Pair map: entry at (y,x) = { code(x), code(min(x+1,W-1)) }, 8B per pixel.
// code (u32) = depth_q16 << 16 | erode_idx << 1 | edge_bit
//   erode_idx: 0 -> weight 0, k in 1..15 -> 0.1 + 0.06*(k-1), 16 -> 1.0
__device__ uint4 g_pair4[B * HW / 2];

// ---------------------------------------------------------------------------
// Exact (rare) fallback: Chebyshev ring scan, returns shell index 2..16
// ---------------------------------------------------------------------------
__device__ __noinline__ unsigned erode_fallback_idx(const float* __restrict__ m,
                                                    int x, int y) {
    for (int r = 4; r <= 45; r++) {
        float mn = 1.0f;
        int xa = max(x - r, 0), xb = min(x + r, W - 1);
        if (y - r >= 0)
            for (int xx = xa; xx <= xb; xx++)
                mn = fminf(mn, __ldg(&m[(y - r) * W + xx]));
        if (y + r < H)
            for (int xx = xa; xx <= xb; xx++)
                mn = fminf(mn, __ldg(&m[(y + r) * W + xx]));
        int ya = max(y - r + 1, 0), yb = min(y + r - 1, H - 1);
        if (x - r >= 0)
            for (int yy = ya; yy <= yb; yy++)
                mn = fminf(mn, __ldg(&m[yy * W + (x - r)]));
        if (x + r < W)
            for (int yy = ya; yy <= yb; yy++)
                mn = fminf(mn, __ldg(&m[yy * W + (x + r)]));
        if (mn == 0.0f) return (unsigned)((r + 2) / 3);   // ceil(r/3)
    }
    return 16u;   // survives all erosions -> weight 1.0
}

// ---------------------------------------------------------------------------
// Kernel 1: bitmap erosion + pair-map packing.  Full-width 1024 x TROWS tiles,
// 256 threads, 256 blocks. Phase 4 widened to 8 px per iteration.
// ---------------------------------------------------------------------------
#define TROWS 16
#define HR (TROWS + 6)       // 22 rows incl. vertical halo

__global__ void pack_kernel(const float* __restrict__ mask,
                            const float* __restrict__ depth,
                            const float* __restrict__ edge,
                            uint4* __restrict__ out4) {
    __shared__ unsigned zb[HR][32];     // zero bitmap (bit=1 -> mask==0)
    __shared__ unsigned hd[HR][32];     // horizontally dilated +/-3
    __shared__ unsigned vd[TROWS][32];  // 7x7 window OR

    const int b = blockIdx.y;
    const int y0 = blockIdx.x * TROWS;
    const int tid = threadIdx.x;
    const float* m  = mask  + (size_t)b * HW;
    const float* dp = depth + (size_t)b * HW;
    const float* eg = edge  + (size_t)b * HW;
    uint2* pp = (uint2*)out4 + (size_t)b * HW;

    // Phase 1: each thread builds one 32-px zero-bit word from 8 float4 loads
    for (int g = tid; g < HR * 32; g += 256) {
        int r = g >> 5, c = g & 31;
        int gy = y0 - 3 + r;
        unsigned wrd = 0;
        if (gy >= 0 && gy < H) {
            const float4* p = (const float4*)&m[gy * W + c * 32];
            #pragma unroll
            for (int j = 0; j < 8; j++) {
                float4 v = __ldcs(&p[j]);
                unsigned nb = (v.x == 0.0f ? 1u : 0u) | (v.y == 0.0f ? 2u : 0u)
                            | (v.z == 0.0f ? 4u : 0u) | (v.w == 0.0f ? 8u : 0u);
                wrd |= nb << (j * 4);
            }
        }
        zb[r][c] = wrd;
    }
    __syncthreads();

    // Phase 2: horizontal dilation by 3 (outside image = no zeros)
    for (int g = tid; g < HR * 32; g += 256) {
        int r = g >> 5, c = g & 31;
        unsigned wm = zb[r][c];
        unsigned L = c ? zb[r][c - 1] : 0u;
        unsigned R = (c < 31) ? zb[r][c + 1] : 0u;
        unsigned h = wm;
        h |= __funnelshift_r(wm, R, 1) | __funnelshift_l(L, wm, 1);
        h |= __funnelshift_r(wm, R, 2) | __funnelshift_l(L, wm, 2);
        h |= __funnelshift_r(wm, R, 3) | __funnelshift_l(L, wm, 3);
        hd[r][c] = h;
    }
    __syncthreads();

    // Phase 3: vertical OR over 7 rows
    for (int g = tid; g < TROWS * 32; g += 256) {
        int r = g >> 5, c = g & 31;
        vd[r][c] = hd[r][c] | hd[r + 1][c] | hd[r + 2][c] | hd[r + 3][c]
                 | hd[r + 4][c] | hd[r + 5][c] | hd[r + 6][c];
    }
    __syncthreads();

    // Phase 4: 8 px per iteration; 9 codes (last = right neighbor, an L1-hit
    // scalar load) -> 8 pairs = 4x uint4 stores.  128 groups per row.
    #pragma unroll 2
    for (int g = tid; g < TROWS * 128; g += 256) {
        int r = g >> 7, q = g & 127;
        int x = q * 8;
        int gy = y0 + r;
        int xe = min(x + 8, W - 1);
        size_t gi = (size_t)gy * W + x;

        float4 d4a = __ldcs((const float4*)&dp[gi]);
        float4 d4b = __ldcs((const float4*)&dp[gi + 4]);
        float4 e4a = __ldcs((const float4*)&eg[gi]);
        float4 e4b = __ldcs((const float4*)&eg[gi + 4]);
        float de = __ldg(&dp[(size_t)gy * W + xe]);
        float ee = __ldg(&eg[(size_t)gy * W + xe]);

        float dvals[9] = {d4a.x, d4a.y, d4a.z, d4a.w,
                          d4b.x, d4b.y, d4b.z, d4b.w, de};
        float evals[9] = {e4a.x, e4a.y, e4a.z, e4a.w,
                          e4b.x, e4b.y, e4b.z, e4b.w, ee};

        // Extract the 9 needed bits in one shot (x is 8-aligned, so bits
        // x..x+8 span at most two 32-bit words).
        unsigned zw0 = zb[r + 3][x >> 5], vw0 = vd[r][x >> 5];
        unsigned zbits = (zw0 >> (x & 31));
        unsigned vbits = (vw0 >> (x & 31));
        if ((x & 31) == 24) {   // need bit 32 from the next word
            unsigned zw1 = ((x >> 5) < 31) ? zb[r + 3][(x >> 5) + 1] : 0u;
            unsigned vw1 = ((x >> 5) < 31) ? vd[r][(x >> 5) + 1] : 0u;
            zbits = (zbits & 0xFFu) | ((zw1 & 1u) << 8);
            vbits = (vbits & 0xFFu) | ((vw1 & 1u) << 8);
        }
        // xe may clamp (x==1016): bit 8 then refers to px 1023 = bit 7
        int last_sh = (xe - x);   // 8 normally, 7 at the right edge

        unsigned code[9];
        #pragma unroll
        for (int i = 0; i < 9; i++) {
            int sh = (i < 8) ? i : last_sh;
            unsigned idx;
            if ((zbits >> sh) & 1u)      idx = 0u;
            else if ((vbits >> sh) & 1u) idx = 1u;
            else                         idx = erode_fallback_idx(m, x + sh, gy);
            unsigned dq = (unsigned)(dvals[i] * 65535.0f + 0.5f);
            code[i] = (dq << 16) | (idx << 1) | (evals[i] != 0.0f ? 1u : 0u);
        }

        uint4* dst = (uint4*)(pp + gi);
        dst[0] = make_uint4(code[0], code[1], code[1], code[2]);
        dst[1] = make_uint4(code[2], code[3], code[3], code[4]);
        dst[2] = make_uint4(code[4], code[5], code[5], code[6]);
        dst[3] = make_uint4(code[6], code[7], code[7], code[8]);
    }
}

// ---------------------------------------------------------------------------
// Kernel 2: fusion — 2 points/thread, 2 pair-gathers per point (R6-proven)
// ---------------------------------------------------------------------------
__device__ __forceinline__ float erode_w(unsigned c) {
    unsigned idx = (c >> 1) & 0x1Fu;
    if (idx == 0u)  return 0.0f;
    if (idx >= 16u) return 1.0f;
    return 0.1f + 0.06f * (float)(idx - 1u);
}

__global__ void __launch_bounds__(256)
fuse_kernel(const uint2* __restrict__ pair,
            const float* __restrict__ xy,
            const float* __restrict__ z,
            const float* __restrict__ occ_body,
            const float* __restrict__ occ_face,
            float* __restrict__ out) {
    int t = blockIdx.x * blockDim.x + threadIdx.x;   // 0 .. B*NPTS/2-1
    int idx0 = t * 2;
    int b = idx0 >> 18;                               // NPTS = 2^18
    int n0 = idx0 & (NPTS - 1);

    const float2 x2  = __ldcs((const float2*)&xy[(size_t)b * 2 * NPTS + n0]);
    const float2 y2  = __ldcs((const float2*)&xy[(size_t)b * 2 * NPTS + NPTS + n0]);
    const uint2* mp = pair + (size_t)b * HW;

    float px[2] = {x2.x, x2.y};
    float py[2] = {y2.x, y2.y};

    int itop[2], ibot[2];
    float wx[2], wy[2];
    #pragma unroll
    for (int i = 0; i < 2; i++) {
        float xf = (px[i] + 1.0f) * 0.5f * (float)(W - 1);
        float yf = (py[i] + 1.0f) * 0.5f * (float)(H - 1);
        float x0f = floorf(xf), y0f = floorf(yf);
        wx[i] = xf - x0f;
        wy[i] = yf - y0f;
        int x0 = min(max((int)x0f, 0), W - 1);
        int y0 = min(max((int)y0f, 0), H - 1);
        int y1 = min(y0 + 1, H - 1);
        itop[i] = y0 * W + x0;
        ibot[i] = y1 * W + x0;
    }

    uint2 tp[2], bp[2];
    #pragma unroll
    for (int i = 0; i < 2; i++) {
        tp[i] = __ldg(&mp[itop[i]]);
        bp[i] = __ldg(&mp[ibot[i]]);
    }
    const float2 z2  = __ldcs((const float2*)&z[idx0]);
    const float2 ob2 = __ldcs((const float2*)&occ_body[idx0]);
    const float2 of2 = __ldcs((const float2*)&occ_face[idx0]);

    float zz[2] = {z2.x, z2.y};
    float ob[2] = {ob2.x, ob2.y};
    float of[2] = {of2.x, of2.y};

    float res[2];
    #pragma unroll
    for (int i = 0; i < 2; i++) {
        unsigned c00 = tp[i].x, c01 = tp[i].y;
        unsigned c10 = bp[i].x, c11 = bp[i].y;

        float w00 = (1.0f - wx[i]) * (1.0f - wy[i]);
        float w01 = wx[i] * (1.0f - wy[i]);
        float w10 = (1.0f - wx[i]) * wy[i];
        float w11 = wx[i] * wy[i];

        float edgev = (float)(c00 & 1u) * w00 + (float)(c01 & 1u) * w01
                    + (float)(c10 & 1u) * w10 + (float)(c11 & 1u) * w11;

        const float s = 1.0f / 65535.0f;
        float dq = (float)(c00 >> 16) * (w00 * s) + (float)(c01 >> 16) * (w01 * s)
                 + (float)(c10 >> 16) * (w10 * s) + (float)(c11 >> 16) * (w11 * s);
        float labels = erode_w(c00) * w00 + erode_w(c01) * w01
                     + erode_w(c10) * w10 + erode_w(c11) * w11;

        float psdf = zz[i] - dq;
        float wgt = __expf(-psdf * psdf * 1000.0f) * labels;
        float r2 = wgt * of[i] + (1.0f - wgt) * ob[i];
        res[i] = (edgev > 0.01f) ? r2 : ob[i];
    }

    __stcs((float2*)&out[idx0], make_float2(res[0], res[1]));
}

// ---------------------------------------------------------------------------
// Launch.  inputs: 0 mask, 1 face_depth, 2 face_depth_edge_mask, 3 xy, 4 z,
//                  5 occ_body, 6 occ_face ; output: [B,1,NPTS] float
// ---------------------------------------------------------------------------
extern "C" void kernel_launch(void* const* d_in, const int* in_sizes, int n_in,
                              void* d_out, int out_size) {
    const float* mask       = (const float*)d_in[0];
    const float* face_depth = (const float*)d_in[1];
    const float* edge_mask  = (const float*)d_in[2];
    const float* xy         = (const float*)d_in[3];
    const float* z          = (const float*)d_in[4];
    const float* occ_body   = (const float*)d_in[5];
    const float* occ_face   = (const float*)d_in[6];
    float* out = (float*)d_out;

    uint4* pair_ptr;
    cudaGetSymbolAddress((void**)&pair_ptr, g_pair4);

    dim3 pg(H / TROWS, B);   // (64, 4) = 256 blocks x 256 threads
    pack_kernel<<<pg, 256>>>(mask, face_depth, edge_mask, pair_ptr);

    int blocks = (B * NPTS / 2) / 256;   // 2048
    fuse_kernel<<<blocks, 256>>>((const uint2*)pair_ptr, xy, z,
                                 occ_body, occ_face, out);
}

// round 17
// speedup vs baseline: 1.5100x; 1.5100x over previous
#include <cuda_runtime.h>
#include <math.h>

#define W 1024
#define H 1024
#define B 4
#define NPTS 262144
#define HW (W * H)

// Pair map: entry at (y,x) = { code(x), code(min(x+1,W-1)) }, 8B per pixel.
// code (u32) = depth_q16 << 16 | erode_idx << 1 | edge_bit
//   erode_idx: 0 -> weight 0, k in 1..15 -> 0.1 + 0.06*(k-1), 16 -> 1.0
__device__ uint4 g_pair4[B * HW / 2];

// ---------------------------------------------------------------------------
// Exact (rare) fallback: Chebyshev ring scan, returns shell index 2..16
// ---------------------------------------------------------------------------
__device__ __noinline__ unsigned erode_fallback_idx(const float* __restrict__ m,
                                                    int x, int y) {
    for (int r = 4; r <= 45; r++) {
        float mn = 1.0f;
        int xa = max(x - r, 0), xb = min(x + r, W - 1);
        if (y - r >= 0)
            for (int xx = xa; xx <= xb; xx++)
                mn = fminf(mn, __ldg(&m[(y - r) * W + xx]));
        if (y + r < H)
            for (int xx = xa; xx <= xb; xx++)
                mn = fminf(mn, __ldg(&m[(y + r) * W + xx]));
        int ya = max(y - r + 1, 0), yb = min(y + r - 1, H - 1);
        if (x - r >= 0)
            for (int yy = ya; yy <= yb; yy++)
                mn = fminf(mn, __ldg(&m[yy * W + (x - r)]));
        if (x + r < W)
            for (int yy = ya; yy <= yb; yy++)
                mn = fminf(mn, __ldg(&m[yy * W + (x + r)]));
        if (mn == 0.0f) return (unsigned)((r + 2) / 3);   // ceil(r/3)
    }
    return 16u;   // survives all erosions -> weight 1.0
}

// ---------------------------------------------------------------------------
// Kernel 1: bitmap erosion + pair-map packing.  Full-width 1024 x TROWS tiles,
// 256 threads, 256 blocks (validated R6 operating point).
// ---------------------------------------------------------------------------
#define TROWS 16
#define HR (TROWS + 6)       // 22 rows incl. vertical halo

__global__ void pack_kernel(const float* __restrict__ mask,
                            const float* __restrict__ depth,
                            const float* __restrict__ edge,
                            uint4* __restrict__ out4) {
    __shared__ unsigned zb[HR][32];     // zero bitmap (bit=1 -> mask==0)
    __shared__ unsigned hd[HR][32];     // horizontally dilated +/-3
    __shared__ unsigned vd[TROWS][32];  // 7x7 window OR

    const int b = blockIdx.y;
    const int y0 = blockIdx.x * TROWS;
    const int tid = threadIdx.x;
    const float* m  = mask  + (size_t)b * HW;
    const float* dp = depth + (size_t)b * HW;
    const float* eg = edge  + (size_t)b * HW;
    uint2* pp = (uint2*)out4 + (size_t)b * HW;

    // Phase 1: each thread builds one 32-px zero-bit word from 8 float4 loads
    for (int g = tid; g < HR * 32; g += 256) {
        int r = g >> 5, c = g & 31;
        int gy = y0 - 3 + r;
        unsigned wrd = 0;
        if (gy >= 0 && gy < H) {
            const float4* p = (const float4*)&m[gy * W + c * 32];
            #pragma unroll
            for (int j = 0; j < 8; j++) {
                float4 v = __ldcs(&p[j]);
                unsigned nb = (v.x == 0.0f ? 1u : 0u) | (v.y == 0.0f ? 2u : 0u)
                            | (v.z == 0.0f ? 4u : 0u) | (v.w == 0.0f ? 8u : 0u);
                wrd |= nb << (j * 4);
            }
        }
        zb[r][c] = wrd;
    }
    __syncthreads();

    // Phase 2: horizontal dilation by 3 (outside image = no zeros)
    for (int g = tid; g < HR * 32; g += 256) {
        int r = g >> 5, c = g & 31;
        unsigned wm = zb[r][c];
        unsigned L = c ? zb[r][c - 1] : 0u;
        unsigned R = (c < 31) ? zb[r][c + 1] : 0u;
        unsigned h = wm;
        h |= __funnelshift_r(wm, R, 1) | __funnelshift_l(L, wm, 1);
        h |= __funnelshift_r(wm, R, 2) | __funnelshift_l(L, wm, 2);
        h |= __funnelshift_r(wm, R, 3) | __funnelshift_l(L, wm, 3);
        hd[r][c] = h;
    }
    __syncthreads();

    // Phase 3: vertical OR over 7 rows
    for (int g = tid; g < TROWS * 32; g += 256) {
        int r = g >> 5, c = g & 31;
        vd[r][c] = hd[r][c] | hd[r + 1][c] | hd[r + 2][c] | hd[r + 3][c]
                 | hd[r + 4][c] | hd[r + 5][c] | hd[r + 6][c];
    }
    __syncthreads();

    // Phase 4: 4 px per iteration; 5 codes (incl. right neighbor, an L1-hit
    // scalar load) -> 4 pairs = 2x uint4 stores.
    #pragma unroll 4
    for (int g = tid; g < TROWS * 256; g += 256) {
        int r = g >> 8, q = g & 255;
        int x = q * 4;
        int gy = y0 + r;
        int xe = min(x + 4, W - 1);
        size_t gi = (size_t)gy * W + x;

        float4 d4 = __ldcs((const float4*)&dp[gi]);
        float4 e4 = __ldcs((const float4*)&eg[gi]);
        float de = __ldg(&dp[(size_t)gy * W + xe]);
        float ee = __ldg(&eg[(size_t)gy * W + xe]);

        float dvals[5] = {d4.x, d4.y, d4.z, d4.w, de};
        float evals[5] = {e4.x, e4.y, e4.z, e4.w, ee};

        unsigned code[5];
        #pragma unroll
        for (int i = 0; i < 5; i++) {
            int xi = (i < 4) ? (x + i) : xe;
            unsigned zbit = (zb[r + 3][xi >> 5] >> (xi & 31)) & 1u;
            unsigned vbit = (vd[r][xi >> 5] >> (xi & 31)) & 1u;
            unsigned idx;
            if (zbit)      idx = 0u;
            else if (vbit) idx = 1u;
            else           idx = erode_fallback_idx(m, xi, gy);   // ~never
            unsigned dq = (unsigned)(dvals[i] * 65535.0f + 0.5f);
            code[i] = (dq << 16) | (idx << 1) | (evals[i] != 0.0f ? 1u : 0u);
        }

        uint4* dst = (uint4*)(pp + gi);
        dst[0] = make_uint4(code[0], code[1], code[1], code[2]);
        dst[1] = make_uint4(code[2], code[3], code[3], code[4]);
    }
}

// ---------------------------------------------------------------------------
// Kernel 2: fusion — 2 points/thread, 2 pair-gathers per point (R6-proven)
// ---------------------------------------------------------------------------
__device__ __forceinline__ float erode_w(unsigned c) {
    unsigned idx = (c >> 1) & 0x1Fu;
    if (idx == 0u)  return 0.0f;
    if (idx >= 16u) return 1.0f;
    return 0.1f + 0.06f * (float)(idx - 1u);
}

__global__ void __launch_bounds__(256)
fuse_kernel(const uint2* __restrict__ pair,
            const float* __restrict__ xy,
            const float* __restrict__ z,
            const float* __restrict__ occ_body,
            const float* __restrict__ occ_face,
            float* __restrict__ out) {
    int t = blockIdx.x * blockDim.x + threadIdx.x;   // 0 .. B*NPTS/2-1
    int idx0 = t * 2;
    int b = idx0 >> 18;                               // NPTS = 2^18
    int n0 = idx0 & (NPTS - 1);

    const float2 x2  = __ldcs((const float2*)&xy[(size_t)b * 2 * NPTS + n0]);
    const float2 y2  = __ldcs((const float2*)&xy[(size_t)b * 2 * NPTS + NPTS + n0]);
    const uint2* mp = pair + (size_t)b * HW;

    float px[2] = {x2.x, x2.y};
    float py[2] = {y2.x, y2.y};

    int itop[2], ibot[2];
    float wx[2], wy[2];
    #pragma unroll
    for (int i = 0; i < 2; i++) {
        float xf = (px[i] + 1.0f) * 0.5f * (float)(W - 1);
        float yf = (py[i] + 1.0f) * 0.5f * (float)(H - 1);
        float x0f = floorf(xf), y0f = floorf(yf);
        wx[i] = xf - x0f;
        wy[i] = yf - y0f;
        int x0 = min(max((int)x0f, 0), W - 1);
        int y0 = min(max((int)y0f, 0), H - 1);
        int y1 = min(y0 + 1, H - 1);
        itop[i] = y0 * W + x0;
        ibot[i] = y1 * W + x0;
    }

    uint2 tp[2], bp[2];
    #pragma unroll
    for (int i = 0; i < 2; i++) {
        tp[i] = __ldg(&mp[itop[i]]);
        bp[i] = __ldg(&mp[ibot[i]]);
    }
    const float2 z2  = __ldcs((const float2*)&z[idx0]);
    const float2 ob2 = __ldcs((const float2*)&occ_body[idx0]);
    const float2 of2 = __ldcs((const float2*)&occ_face[idx0]);

    float zz[2] = {z2.x, z2.y};
    float ob[2] = {ob2.x, ob2.y};
    float of[2] = {of2.x, of2.y};

    float res[2];
    #pragma unroll
    for (int i = 0; i < 2; i++) {
        unsigned c00 = tp[i].x, c01 = tp[i].y;
        unsigned c10 = bp[i].x, c11 = bp[i].y;

        float w00 = (1.0f - wx[i]) * (1.0f - wy[i]);
        float w01 = wx[i] * (1.0f - wy[i]);
        float w10 = (1.0f - wx[i]) * wy[i];
        float w11 = wx[i] * wy[i];

        float edgev = (float)(c00 & 1u) * w00 + (float)(c01 & 1u) * w01
                    + (float)(c10 & 1u) * w10 + (float)(c11 & 1u) * w11;

        const float s = 1.0f / 65535.0f;
        float dq = (float)(c00 >> 16) * (w00 * s) + (float)(c01 >> 16) * (w01 * s)
                 + (float)(c10 >> 16) * (w10 * s) + (float)(c11 >> 16) * (w11 * s);
        float labels = erode_w(c00) * w00 + erode_w(c01) * w01
                     + erode_w(c10) * w10 + erode_w(c11) * w11;

        float psdf = zz[i] - dq;
        float wgt = __expf(-psdf * psdf * 1000.0f) * labels;
        float r2 = wgt * of[i] + (1.0f - wgt) * ob[i];
        res[i] = (edgev > 0.01f) ? r2 : ob[i];
    }

    __stcs((float2*)&out[idx0], make_float2(res[0], res[1]));
}

// ---------------------------------------------------------------------------
// Launch.  inputs: 0 mask, 1 face_depth, 2 face_depth_edge_mask, 3 xy, 4 z,
//                  5 occ_body, 6 occ_face ; output: [B,1,NPTS] float
// ---------------------------------------------------------------------------
extern "C" void kernel_launch(void* const* d_in, const int* in_sizes, int n_in,
                              void* d_out, int out_size) {
    const float* mask       = (const float*)d_in[0];
    const float* face_depth = (const float*)d_in[1];
    const float* edge_mask  = (const float*)d_in[2];
    const float* xy         = (const float*)d_in[3];
    const float* z          = (const float*)d_in[4];
    const float* occ_body   = (const float*)d_in[5];
    const float* occ_face   = (const float*)d_in[6];
    float* out = (float*)d_out;

    uint4* pair_ptr;
    cudaGetSymbolAddress((void**)&pair_ptr, g_pair4);

    dim3 pg(H / TROWS, B);   // (64, 4) = 256 blocks x 256 threads
    pack_kernel<<<pg, 256>>>(mask, face_depth, edge_mask, pair_ptr);

    int blocks = (B * NPTS / 2) / 256;   // 2048
    fuse_kernel<<<blocks, 256>>>((const uint2*)pair_ptr, xy, z,
                                 occ_body, occ_face, out);
}